// round 15
// baseline (speedup 1.0000x reference)
#include <cuda_runtime.h>
#include <cuda_fp16.h>
#include <cstdint>

#define D_MODEL 1024
#define NHEAD   16
#define HD      64
#define SEQ     2048
#define BATCH   2
#define M_TOT   (BATCH * SEQ)   // 4096
#define QKV_W   (3 * D_MODEL)   // 3072

// Scratch (no cudaMalloc allowed).
__device__ __half g_qkv[(size_t)M_TOT * QKV_W];        // Q|K|V fp16 [4096][3072]
__device__ __half g_ao [(size_t)M_TOT * D_MODEL];      // attn out fp16
__device__ __half g_xh [(size_t)M_TOT * D_MODEL];      // x -> fp16
__device__ __half g_wqh[(size_t)QKV_W * D_MODEL];      // w_qkv -> fp16
__device__ __half g_woh[(size_t)D_MODEL * D_MODEL];    // w_o -> fp16

// fp16 mma: D(fp32) += A(f16 m16k16 row) x B(f16 k16n8 col)
__device__ __forceinline__ void mma_f16(float* c, const unsigned* a,
                                        unsigned b0, unsigned b1) {
    asm volatile(
        "mma.sync.aligned.m16n8k16.row.col.f32.f16.f16.f32 "
        "{%0,%1,%2,%3},{%4,%5,%6,%7},{%8,%9},{%0,%1,%2,%3};\n"
        : "+f"(c[0]), "+f"(c[1]), "+f"(c[2]), "+f"(c[3])
        : "r"(a[0]), "r"(a[1]), "r"(a[2]), "r"(a[3]), "r"(b0), "r"(b1));
}

__device__ __forceinline__ void ldsm4(unsigned& r0, unsigned& r1,
                                      unsigned& r2, unsigned& r3, unsigned addr) {
    asm volatile("ldmatrix.sync.aligned.m8n8.x4.shared.b16 {%0,%1,%2,%3}, [%4];"
                 : "=r"(r0), "=r"(r1), "=r"(r2), "=r"(r3) : "r"(addr));
}

// transposing variant: from row-major M[s][d] produces B-frags with k=s, n=d
__device__ __forceinline__ void ldsm4t(unsigned& r0, unsigned& r1,
                                       unsigned& r2, unsigned& r3, unsigned addr) {
    asm volatile("ldmatrix.sync.aligned.m8n8.x4.trans.shared.b16 {%0,%1,%2,%3}, [%4];"
                 : "=r"(r0), "=r"(r1), "=r"(r2), "=r"(r3) : "r"(addr));
}

__device__ __forceinline__ float fexp2(float x) {
    float r;
    asm("ex2.approx.ftz.f32 %0, %1;" : "=f"(r) : "f"(x));
    return r;
}

__device__ __forceinline__ void cp_async16(void* smem_dst, const void* gmem_src) {
    unsigned s = (unsigned)__cvta_generic_to_shared(smem_dst);
    asm volatile("cp.async.cg.shared.global [%0], [%1], 16;\n" :: "r"(s), "l"(gmem_src));
}
#define CP_COMMIT() asm volatile("cp.async.commit_group;\n" ::: "memory")
#define CP_WAIT1()  asm volatile("cp.async.wait_group 1;\n" ::: "memory")
#define CP_WAIT0()  asm volatile("cp.async.wait_group 0;\n" ::: "memory")

// ---------------------------------------------------------------------------
// fp32 -> fp16 pre-pass (x, w_qkv, w_o)
// ---------------------------------------------------------------------------
#define XC_F4 ((M_TOT * D_MODEL) / 4)
#define WQ_F4 ((QKV_W * D_MODEL) / 4)
#define WO_F4 ((D_MODEL * D_MODEL) / 4)
#define CONV_BLOCKS ((XC_F4 + WQ_F4 + WO_F4) / 256)

__global__ void conv_h(const float4* __restrict__ x,
                       const float4* __restrict__ wq,
                       const float4* __restrict__ wo,
                       uint2* __restrict__ ox,
                       uint2* __restrict__ owq,
                       uint2* __restrict__ owo) {
    const int idx = blockIdx.x * 256 + threadIdx.x;
    const float4* src;
    uint2* dst;
    int i;
    if (idx < XC_F4)                { src = x;  dst = ox;  i = idx; }
    else if (idx < XC_F4 + WQ_F4)   { src = wq; dst = owq; i = idx - XC_F4; }
    else                            { src = wo; dst = owo; i = idx - XC_F4 - WQ_F4; }
    float4 v = src[i];
    __half2 lo = __floats2half2_rn(v.x, v.y);
    __half2 hi = __floats2half2_rn(v.z, v.w);
    dst[i] = make_uint2(*(unsigned*)&lo, *(unsigned*)&hi);
}

// ---------------------------------------------------------------------------
// fp16 GEMM with ldmatrix fragment loads.
// 128x128 block tile, K-tile 64 halves, 256 threads (8 warps, 64x32 tiles),
// 3-stage cp.async pipeline, ONE __syncthreads per K-tile, 2 CTAs/SM.
// OUT_HALF: write C as fp16 (uniform, coalesced) else fp32.
// ---------------------------------------------------------------------------
#define NSTAGE 3
#define GSTR 36                 // u32 per smem row (32 data + 4 pad)
#define GTILE (128 * GSTR)
#define SMEM_GEMM (2 * NSTAGE * GTILE * 4)   // 110592 B

template <bool OUT_HALF>
__global__ __launch_bounds__(256, 2)
void gemm_h(const __half* __restrict__ A, const __half* __restrict__ B,
            void* __restrict__ Cv, int M, int N, int K) {
    extern __shared__ unsigned smg[];
    unsigned* Abuf = smg;
    unsigned* Bbuf = smg + NSTAGE * GTILE;
    const unsigned smb = (unsigned)__cvta_generic_to_shared(smg);

    const int t    = threadIdx.x;
    const int lane = t & 31;
    const int w    = t >> 5;
    const int gid  = lane >> 2;
    const int tig  = lane & 3;
    const int wm   = w & 1;
    const int wn   = w >> 1;
    const int m0   = blockIdx.y * 128;
    const int n0   = blockIdx.x * 128;

    const int li  = lane & 7;
    const int q8  = (lane >> 3) & 1;
    const int q16 = lane >> 4;
    const unsigned aLane = ((unsigned)((wm * 64 + q8 * 8 + li) * GSTR + q16 * 4)) * 4;
    const unsigned bLane = ((unsigned)((wn * 32 + q16 * 8 + li) * GSTR + q8 * 4)) * 4;

    float acc[4][4][4];
#pragma unroll
    for (int i = 0; i < 4; i++)
#pragma unroll
        for (int j = 0; j < 4; j++)
#pragma unroll
            for (int e = 0; e < 4; e++) acc[i][j][e] = 0.f;

    const int nkt = K / 64;

    auto issue = [&](int stage, int kt) {
        unsigned* as = Abuf + stage * GTILE;
        unsigned* bs = Bbuf + stage * GTILE;
        const __half* Ag = A + (size_t)m0 * K + kt * 64;
        const __half* Bg = B + (size_t)n0 * K + kt * 64;
#pragma unroll
        for (int i = 0; i < 4; i++) {
            const int c = t + i * 256;           // 0..1023
            const int row = c >> 3, cc = c & 7;
            cp_async16(&as[row * GSTR + cc * 4], Ag + (size_t)row * K + cc * 8);
            cp_async16(&bs[row * GSTR + cc * 4], Bg + (size_t)row * K + cc * 8);
        }
    };

    issue(0, 0); CP_COMMIT();
    issue(1, 1); CP_COMMIT();

    int stage = 0;
    for (int kt = 0; kt < nkt; kt++) {
        if (kt + 1 < nkt) { CP_WAIT1(); } else { CP_WAIT0(); }
        __syncthreads();   // tile kt visible; all warps done with buf (kt-1)%3

        const unsigned aBase = smb + (unsigned)(stage * GTILE) * 4 + aLane;
        const unsigned bBase = smb + (unsigned)((NSTAGE + stage) * GTILE) * 4 + bLane;

        // s=0 fragments first: start the LDSM->HMMA chain before LSU work
        unsigned av[4][4], bv[4][2];
#pragma unroll
        for (int mi = 0; mi < 4; mi++)
            ldsm4(av[mi][0], av[mi][1], av[mi][2], av[mi][3],
                  aBase + mi * (16 * GSTR * 4));
        ldsm4(bv[0][0], bv[0][1], bv[1][0], bv[1][1], bBase);
        ldsm4(bv[2][0], bv[2][1], bv[3][0], bv[3][1], bBase + 16 * GSTR * 4);

        if (kt + 2 < nkt) {
            int ns = stage + 2; if (ns >= NSTAGE) ns -= NSTAGE;
            issue(ns, kt + 2);
            CP_COMMIT();
        }

#pragma unroll
        for (int mi = 0; mi < 4; mi++)
#pragma unroll
            for (int nj = 0; nj < 4; nj++)
                mma_f16(acc[mi][nj], av[mi], bv[nj][0], bv[nj][1]);

#pragma unroll
        for (int s = 1; s < 4; s++) {
#pragma unroll
            for (int mi = 0; mi < 4; mi++)
                ldsm4(av[mi][0], av[mi][1], av[mi][2], av[mi][3],
                      aBase + mi * (16 * GSTR * 4) + s * 32);
            ldsm4(bv[0][0], bv[0][1], bv[1][0], bv[1][1], bBase + s * 32);
            ldsm4(bv[2][0], bv[2][1], bv[3][0], bv[3][1],
                  bBase + 16 * GSTR * 4 + s * 32);
#pragma unroll
            for (int mi = 0; mi < 4; mi++)
#pragma unroll
                for (int nj = 0; nj < 4; nj++)
                    mma_f16(acc[mi][nj], av[mi], bv[nj][0], bv[nj][1]);
        }
        stage++; if (stage >= NSTAGE) stage -= NSTAGE;
    }

    // epilogue (uniform, coalesced)
#pragma unroll
    for (int mi = 0; mi < 4; mi++) {
        const int r = m0 + wm * 64 + 16 * mi + gid;
#pragma unroll
        for (int nj = 0; nj < 4; nj++) {
            const int c = n0 + wn * 32 + 8 * nj + 2 * tig;
            if (OUT_HALF) {
                __half2* C = (__half2*)Cv;
                C[((size_t)r * N + c) >> 1] =
                    __floats2half2_rn(acc[mi][nj][0], acc[mi][nj][1]);
                C[((size_t)(r + 8) * N + c) >> 1] =
                    __floats2half2_rn(acc[mi][nj][2], acc[mi][nj][3]);
            } else {
                float* C = (float*)Cv;
                *(float2*)(C + (size_t)r * N + c) =
                    make_float2(acc[mi][nj][0], acc[mi][nj][1]);
                *(float2*)(C + (size_t)(r + 8) * N + c) =
                    make_float2(acc[mi][nj][2], acc[mi][nj][3]);
            }
        }
    }
}

// ---------------------------------------------------------------------------
// Causal flash attention, all-fp16 mma, register-resident P, ldmatrix frags.
// V stored ROW-MAJOR [s][d]; P.V B-fragments via ldmatrix.trans (free transpose).
// 128-query tiles, 256 threads (8 warps x 16 rows), paired key tiles
// (4 buffers, one wait+sync per 2 tiles), per-warp causal skip, base-2 softmax.
// LOAD BALANCE: each block runs q-tiles (NQT-1-bx) then bx -> uniform wave.
// ---------------------------------------------------------------------------
#define AKS 36
#define AKS_ELEMS (64 * AKS)
#define AVS 36
#define AVS_ELEMS (64 * AVS)
#define AQS 36
#define QROWS 128
#define NQT (SEQ / QROWS)     // 16
#define SMEM_ATTN ((4 * AKS_ELEMS + 4 * AVS_ELEMS + QROWS * AQS) * 4)   // 92160 B

__global__ __launch_bounds__(256)
void attn_h(const __half* __restrict__ qkv, __half* __restrict__ out) {
    extern __shared__ unsigned sma[];
    unsigned* KsB = sma;                                 // [4][64 s][AKS]
    unsigned* VsB = sma + 4 * AKS_ELEMS;                 // [4][64 s][AVS] row-major
    unsigned* Qs  = sma + 4 * AKS_ELEMS + 4 * AVS_ELEMS; // [128][AQS]
    const unsigned smb = (unsigned)__cvta_generic_to_shared(sma);

    const int h    = blockIdx.y;
    const int b    = blockIdx.z;
    const int t    = threadIdx.x;
    const int lane = t & 31;
    const int w    = t >> 5;        // 0..7
    const int gid  = lane >> 2;
    const int tig  = lane & 3;

    const int li  = lane & 7;
    const int q8  = (lane >> 3) & 1;
    const int q16 = lane >> 4;
    // K frags (non-trans): rows = key index, col add = q8*4 u32
    const unsigned kLane = ((unsigned)((q16 * 8 + li) * AKS + q8 * 4)) * 4;
    // V frags (trans, row-major [s][d]): rows = s = q8*8+li, col add = q16*8 halves
    const unsigned vLane = ((unsigned)((q8 * 8 + li) * AVS)) * 4 + q16 * 16;

    const __half* kbase = qkv + (size_t)(b * SEQ) * QKV_W + D_MODEL + h * HD;
    const __half* vbase = qkv + (size_t)(b * SEQ) * QKV_W + 2 * D_MODEL + h * HD;

    auto load_kv = [&](int nb, int jt) {
        const __half* kp = kbase + (size_t)jt * 64 * QKV_W;
        const __half* vp = vbase + (size_t)jt * 64 * QKV_W;
#pragma unroll
        for (int i = 0; i < 2; i++) {       // K: 64 rows x 8 chunks = 512
            const int c = t + i * 256;
            const int row = c >> 3, cc = c & 7;
            cp_async16(&KsB[nb * AKS_ELEMS + row * AKS + cc * 4],
                       kp + (size_t)row * QKV_W + cc * 8);
        }
#pragma unroll
        for (int i = 0; i < 2; i++) {       // V: 64 s-rows x 8 chunks = 512
            const int c = t + i * 256;
            const int row = c >> 3, cc = c & 7;
            cp_async16(&VsB[nb * AVS_ELEMS + row * AVS + cc * 4],
                       vp + (size_t)row * QKV_W + cc * 8);
        }
    };

    for (int leg = 0; leg < 2; leg++) {
        const int qt = leg ? (int)blockIdx.x : (NQT - 1 - (int)blockIdx.x);
        const int q0 = qt * QROWS;

        __syncthreads();   // previous leg's buffer reads fully done

        // prologue: Q tile (128 rows) + key-tile pair 0 (tiles 0,1 -> bufs 0,1)
        {
            const __half* qp = qkv + (size_t)(b * SEQ + q0) * QKV_W + h * HD;
#pragma unroll
            for (int i = 0; i < 4; i++) {       // Q: 128 rows x 8 chunks = 1024
                const int c = t + i * 256;
                const int row = c >> 3, cc = c & 7;
                cp_async16(&Qs[row * AQS + cc * 4], qp + (size_t)row * QKV_W + cc * 8);
            }
            load_kv(0, 0);
            load_kv(1, 1);
        }
        CP_COMMIT();
        CP_WAIT0();
        __syncthreads();

        // Q fragments -> registers, scaled by 0.125*log2(e) (base-2 softmax)
        unsigned qf[4][4];
        {
            const __half2 sc = __float2half2_rn(0.125f * 1.44269504f);
            const int r0 = (16 * w + gid) * AQS;
            const int r1 = (16 * w + gid + 8) * AQS;
#pragma unroll
            for (int s = 0; s < 4; s++) {
                unsigned u0 = Qs[r0 + 8 * s + tig];
                unsigned u1 = Qs[r1 + 8 * s + tig];
                unsigned u2 = Qs[r0 + 8 * s + tig + 4];
                unsigned u3 = Qs[r1 + 8 * s + tig + 4];
                __half2 h0 = __hmul2(*(__half2*)&u0, sc);
                __half2 h1 = __hmul2(*(__half2*)&u1, sc);
                __half2 h2 = __hmul2(*(__half2*)&u2, sc);
                __half2 h3 = __hmul2(*(__half2*)&u3, sc);
                qf[s][0] = *(unsigned*)&h0;
                qf[s][1] = *(unsigned*)&h1;
                qf[s][2] = *(unsigned*)&h2;
                qf[s][3] = *(unsigned*)&h3;
            }
        }

        float o[8][4];
#pragma unroll
        for (int j = 0; j < 8; j++)
#pragma unroll
            for (int e = 0; e < 4; e++) o[j][e] = 0.f;
        float m0 = -1e30f, m1 = -1e30f, l0 = 0.f, l1 = 0.f;

        const int row0    = q0 + 16 * w + gid;
        const int rowWmin = q0 + 16 * w;
        const int rowWmax = rowWmin + 15;
        const int npair   = qt + 1;

        for (int p = 0; p < npair; p++) {
            CP_WAIT0();
            __syncthreads();

            if (p + 1 < npair) {
                const int nb = 2 * ((p + 1) & 1);
                load_kv(nb,     2 * p + 2);
                load_kv(nb + 1, 2 * p + 3);
                CP_COMMIT();
            }

#pragma unroll
            for (int half = 0; half < 2; half++) {
                const int jt = 2 * p + half;
                const int k0 = jt * 64;
                if (k0 > rowWmax) continue;   // fully above diagonal: exact no-op

                const int buf = 2 * (p & 1) + half;
                const unsigned kBase = smb + (unsigned)(buf * AKS_ELEMS) * 4 + kLane;
                const unsigned vBase = smb + (unsigned)(4 * AKS_ELEMS + buf * AVS_ELEMS) * 4 + vLane;

                // S = Q K^T
                float sacc[8][4];
#pragma unroll
                for (int j = 0; j < 8; j++)
#pragma unroll
                    for (int e = 0; e < 4; e++) sacc[j][e] = 0.f;

#pragma unroll
                for (int s = 0; s < 4; s++) {
#pragma unroll
                    for (int pp = 0; pp < 4; pp++) {
                        unsigned k0r, k1r, k2r, k3r;
                        ldsm4(k0r, k1r, k2r, k3r, kBase + pp * (16 * AKS * 4) + s * 32);
                        mma_f16(sacc[2 * pp],     qf[s], k0r, k1r);
                        mma_f16(sacc[2 * pp + 1], qf[s], k2r, k3r);
                    }
                }

                // mask + row max
                const bool need_mask = (k0 + 63 > rowWmin);
                float mt0 = -1e30f, mt1 = -1e30f;
#pragma unroll
                for (int j = 0; j < 8; j++) {
                    const int cb = k0 + 8 * j + 2 * tig;
                    if (need_mask) {
                        if (cb     > row0)     sacc[j][0] = -1e30f;
                        if (cb + 1 > row0)     sacc[j][1] = -1e30f;
                        if (cb     > row0 + 8) sacc[j][2] = -1e30f;
                        if (cb + 1 > row0 + 8) sacc[j][3] = -1e30f;
                    }
                    mt0 = fmaxf(mt0, fmaxf(sacc[j][0], sacc[j][1]));
                    mt1 = fmaxf(mt1, fmaxf(sacc[j][2], sacc[j][3]));
                }
                mt0 = fmaxf(mt0, __shfl_xor_sync(0xffffffffu, mt0, 1));
                mt0 = fmaxf(mt0, __shfl_xor_sync(0xffffffffu, mt0, 2));
                mt1 = fmaxf(mt1, __shfl_xor_sync(0xffffffffu, mt1, 1));
                mt1 = fmaxf(mt1, __shfl_xor_sync(0xffffffffu, mt1, 2));

                const float mn0 = fmaxf(m0, mt0);
                const float mn1 = fmaxf(m1, mt1);
                const float al0 = fexp2(m0 - mn0);
                const float al1 = fexp2(m1 - mn1);
                m0 = mn0; m1 = mn1;

                // P = 2^(S - m): fp16 A-fragments in registers
                unsigned pf[4][4];
                float ls0 = 0.f, ls1 = 0.f;
#pragma unroll
                for (int j = 0; j < 8; j++) {
                    float p00 = fexp2(sacc[j][0] - mn0);
                    float p01 = fexp2(sacc[j][1] - mn0);
                    float p10 = fexp2(sacc[j][2] - mn1);
                    float p11 = fexp2(sacc[j][3] - mn1);
                    ls0 += p00 + p01;
                    ls1 += p10 + p11;
                    __half2 lo = __floats2half2_rn(p00, p01);
                    __half2 hi = __floats2half2_rn(p10, p11);
                    const int mm = j >> 1;
                    const int off = (j & 1) << 1;
                    pf[mm][off]     = *(unsigned*)&lo;
                    pf[mm][off + 1] = *(unsigned*)&hi;
                }
                ls0 += __shfl_xor_sync(0xffffffffu, ls0, 1);
                ls0 += __shfl_xor_sync(0xffffffffu, ls0, 2);
                ls1 += __shfl_xor_sync(0xffffffffu, ls1, 1);
                ls1 += __shfl_xor_sync(0xffffffffu, ls1, 2);
                l0 = l0 * al0 + ls0;
                l1 = l1 * al1 + ls1;

#pragma unroll
                for (int j = 0; j < 8; j++) {
                    o[j][0] *= al0; o[j][1] *= al0;
                    o[j][2] *= al1; o[j][3] *= al1;
                }

                // O += P V  (B-frags via trans ldmatrix from row-major V[s][d])
#pragma unroll
                for (int mm = 0; mm < 4; mm++) {
#pragma unroll
                    for (int pp = 0; pp < 4; pp++) {
                        unsigned v0, v1, v2, v3;
                        ldsm4t(v0, v1, v2, v3,
                               vBase + mm * (16 * AVS * 4) + pp * 32);
                        mma_f16(o[2 * pp],     pf[mm], v0, v1);
                        mma_f16(o[2 * pp + 1], pf[mm], v2, v3);
                    }
                }
            }
        }

        // epilogue -> fp16 for the output projection
        const float i0 = 1.f / l0;
        const float i1 = 1.f / l1;
        __half2* op0 = (__half2*)(out + (size_t)(b * SEQ + row0) * D_MODEL + h * HD);
        __half2* op1 = (__half2*)(out + (size_t)(b * SEQ + row0 + 8) * D_MODEL + h * HD);
#pragma unroll
        for (int j = 0; j < 8; j++) {
            const int c = (8 * j + 2 * tig) >> 1;
            op0[c] = __floats2half2_rn(o[j][0] * i0, o[j][1] * i0);
            op1[c] = __floats2half2_rn(o[j][2] * i1, o[j][3] * i1);
        }
    }
}

extern "C" void kernel_launch(void* const* d_in, const int* in_sizes, int n_in,
                              void* d_out, int out_size) {
    const float* x     = (const float*)d_in[0];
    const float* w_qkv = (const float*)d_in[1];
    const float* w_o   = (const float*)d_in[2];
    float* out         = (float*)d_out;

    __half *qkvh, *ao, *xh, *wqh, *woh;
    cudaGetSymbolAddress((void**)&qkvh, g_qkv);
    cudaGetSymbolAddress((void**)&ao,   g_ao);
    cudaGetSymbolAddress((void**)&xh,   g_xh);
    cudaGetSymbolAddress((void**)&wqh,  g_wqh);
    cudaGetSymbolAddress((void**)&woh,  g_woh);

    static bool attr_set = false;
    if (!attr_set) {
        cudaFuncSetAttribute(gemm_h<true>,  cudaFuncAttributeMaxDynamicSharedMemorySize, SMEM_GEMM);
        cudaFuncSetAttribute(gemm_h<false>, cudaFuncAttributeMaxDynamicSharedMemorySize, SMEM_GEMM);
        cudaFuncSetAttribute(attn_h, cudaFuncAttributeMaxDynamicSharedMemorySize, SMEM_ATTN);
        attr_set = true;
    }

    // 0) fp32 -> fp16 pre-pass
    conv_h<<<CONV_BLOCKS, 256>>>((const float4*)x, (const float4*)w_qkv, (const float4*)w_o,
                                 (uint2*)xh, (uint2*)wqh, (uint2*)woh);

    // 1) QKV projection (fp16 mma) -> Q|K|V fp16 row-major [4096][3072]
    gemm_h<true><<<dim3(QKV_W / 128, M_TOT / 128), 256, SMEM_GEMM>>>(
        xh, wqh, qkvh, M_TOT, QKV_W, D_MODEL);

    // 2) causal attention -> fp16 (paired q-tiles: uniform work per block)
    attn_h<<<dim3(NQT / 2, NHEAD, BATCH), 256, SMEM_ATTN>>>(qkvh, ao);

    // 3) output projection (fp16 mma) -> fp32
    gemm_h<false><<<dim3(D_MODEL / 128, M_TOT / 128), 256, SMEM_GEMM>>>(
        ao, woh, out, M_TOT, D_MODEL, D_MODEL);
}

// round 16
// speedup vs baseline: 1.0614x; 1.0614x over previous
#include <cuda_runtime.h>
#include <cuda_fp16.h>
#include <cstdint>

#define D_MODEL 1024
#define NHEAD   16
#define HD      64
#define SEQ     2048
#define BATCH   2
#define M_TOT   (BATCH * SEQ)   // 4096
#define QKV_W   (3 * D_MODEL)   // 3072

// Scratch (no cudaMalloc allowed).
__device__ __half g_qkh[(size_t)M_TOT * 2 * D_MODEL];  // Q|K fp16 [4096][2048]
__device__ __half g_vt [(size_t)M_TOT * D_MODEL];      // V^T fp16 [(b*1024+d)][2048 s]
__device__ __half g_ao [(size_t)M_TOT * D_MODEL];      // attn out fp16
__device__ __half g_xh [(size_t)M_TOT * D_MODEL];      // x -> fp16
__device__ __half g_wqh[(size_t)QKV_W * D_MODEL];      // w_qkv -> fp16
__device__ __half g_woh[(size_t)D_MODEL * D_MODEL];    // w_o -> fp16

// fp16 mma: D(fp32) += A(f16 m16k16 row) x B(f16 k16n8 col)
__device__ __forceinline__ void mma_f16(float* c, const unsigned* a,
                                        unsigned b0, unsigned b1) {
    asm volatile(
        "mma.sync.aligned.m16n8k16.row.col.f32.f16.f16.f32 "
        "{%0,%1,%2,%3},{%4,%5,%6,%7},{%8,%9},{%0,%1,%2,%3};\n"
        : "+f"(c[0]), "+f"(c[1]), "+f"(c[2]), "+f"(c[3])
        : "r"(a[0]), "r"(a[1]), "r"(a[2]), "r"(a[3]), "r"(b0), "r"(b1));
}

__device__ __forceinline__ void ldsm4(unsigned& r0, unsigned& r1,
                                      unsigned& r2, unsigned& r3, unsigned addr) {
    asm volatile("ldmatrix.sync.aligned.m8n8.x4.shared.b16 {%0,%1,%2,%3}, [%4];"
                 : "=r"(r0), "=r"(r1), "=r"(r2), "=r"(r3) : "r"(addr));
}

__device__ __forceinline__ float fexp2(float x) {
    float r;
    asm("ex2.approx.ftz.f32 %0, %1;" : "=f"(r) : "f"(x));
    return r;
}

__device__ __forceinline__ void cp_async16(void* smem_dst, const void* gmem_src) {
    unsigned s = (unsigned)__cvta_generic_to_shared(smem_dst);
    asm volatile("cp.async.cg.shared.global [%0], [%1], 16;\n" :: "r"(s), "l"(gmem_src));
}
#define CP_COMMIT() asm volatile("cp.async.commit_group;\n" ::: "memory")
#define CP_WAIT1()  asm volatile("cp.async.wait_group 1;\n" ::: "memory")
#define CP_WAIT0()  asm volatile("cp.async.wait_group 0;\n" ::: "memory")

// ---------------------------------------------------------------------------
// fp32 -> fp16 pre-pass (x, w_qkv, w_o)
// ---------------------------------------------------------------------------
#define XC_F4 ((M_TOT * D_MODEL) / 4)
#define WQ_F4 ((QKV_W * D_MODEL) / 4)
#define WO_F4 ((D_MODEL * D_MODEL) / 4)
#define CONV_BLOCKS ((XC_F4 + WQ_F4 + WO_F4) / 256)

__global__ void conv_h(const float4* __restrict__ x,
                       const float4* __restrict__ wq,
                       const float4* __restrict__ wo,
                       uint2* __restrict__ ox,
                       uint2* __restrict__ owq,
                       uint2* __restrict__ owo) {
    const int idx = blockIdx.x * 256 + threadIdx.x;
    const float4* src;
    uint2* dst;
    int i;
    if (idx < XC_F4)                { src = x;  dst = ox;  i = idx; }
    else if (idx < XC_F4 + WQ_F4)   { src = wq; dst = owq; i = idx - XC_F4; }
    else                            { src = wo; dst = owo; i = idx - XC_F4 - WQ_F4; }
    float4 v = src[i];
    __half2 lo = __floats2half2_rn(v.x, v.y);
    __half2 hi = __floats2half2_rn(v.z, v.w);
    dst[i] = make_uint2(*(unsigned*)&lo, *(unsigned*)&hi);
}

// ---------------------------------------------------------------------------
// fp16 GEMM with ldmatrix fragment loads.
// 128x128 block tile, K-tile 64 halves, 256 threads (8 warps, 64x32 tiles),
// 3-stage cp.async pipeline, ONE __syncthreads per K-tile, 2 CTAs/SM.
// MODE 0: fp32 out -> C0.
// MODE 1: cols<2048 -> fp16 C0 (Q|K, stride 2048); cols>=2048 -> V^T fp16 C1.
// ---------------------------------------------------------------------------
#define NSTAGE 3
#define GSTR 36                 // u32 per smem row (32 data + 4 pad)
#define GTILE (128 * GSTR)
#define SMEM_GEMM (2 * NSTAGE * GTILE * 4)   // 110592 B

template <int MODE>
__global__ __launch_bounds__(256, 2)
void gemm_h(const __half* __restrict__ A, const __half* __restrict__ B,
            void* __restrict__ C0, void* __restrict__ C1, int M, int N, int K) {
    extern __shared__ unsigned smg[];
    unsigned* Abuf = smg;
    unsigned* Bbuf = smg + NSTAGE * GTILE;
    const unsigned smb = (unsigned)__cvta_generic_to_shared(smg);

    const int t    = threadIdx.x;
    const int lane = t & 31;
    const int w    = t >> 5;
    const int gid  = lane >> 2;
    const int tig  = lane & 3;
    const int wm   = w & 1;
    const int wn   = w >> 1;
    const int m0   = blockIdx.y * 128;
    const int n0   = blockIdx.x * 128;

    const int li  = lane & 7;
    const int q8  = (lane >> 3) & 1;
    const int q16 = lane >> 4;
    const unsigned aLane = ((unsigned)((wm * 64 + q8 * 8 + li) * GSTR + q16 * 4)) * 4;
    const unsigned bLane = ((unsigned)((wn * 32 + q16 * 8 + li) * GSTR + q8 * 4)) * 4;

    float acc[4][4][4];
#pragma unroll
    for (int i = 0; i < 4; i++)
#pragma unroll
        for (int j = 0; j < 4; j++)
#pragma unroll
            for (int e = 0; e < 4; e++) acc[i][j][e] = 0.f;

    const int nkt = K / 64;

    auto issue = [&](int stage, int kt) {
        unsigned* as = Abuf + stage * GTILE;
        unsigned* bs = Bbuf + stage * GTILE;
        const __half* Ag = A + (size_t)m0 * K + kt * 64;
        const __half* Bg = B + (size_t)n0 * K + kt * 64;
#pragma unroll
        for (int i = 0; i < 4; i++) {
            const int c = t + i * 256;           // 0..1023
            const int row = c >> 3, cc = c & 7;
            cp_async16(&as[row * GSTR + cc * 4], Ag + (size_t)row * K + cc * 8);
            cp_async16(&bs[row * GSTR + cc * 4], Bg + (size_t)row * K + cc * 8);
        }
    };

    issue(0, 0); CP_COMMIT();
    issue(1, 1); CP_COMMIT();

    int stage = 0;
    for (int kt = 0; kt < nkt; kt++) {
        if (kt + 1 < nkt) { CP_WAIT1(); } else { CP_WAIT0(); }
        __syncthreads();   // tile kt visible; all warps done with buf (kt-1)%3

        const unsigned aBase = smb + (unsigned)(stage * GTILE) * 4 + aLane;
        const unsigned bBase = smb + (unsigned)((NSTAGE + stage) * GTILE) * 4 + bLane;

        // s=0 fragments first: start the LDSM->HMMA chain before LSU work
        unsigned av[4][4], bv[4][2];
#pragma unroll
        for (int mi = 0; mi < 4; mi++)
            ldsm4(av[mi][0], av[mi][1], av[mi][2], av[mi][3],
                  aBase + mi * (16 * GSTR * 4));
        ldsm4(bv[0][0], bv[0][1], bv[1][0], bv[1][1], bBase);
        ldsm4(bv[2][0], bv[2][1], bv[3][0], bv[3][1], bBase + 16 * GSTR * 4);

        if (kt + 2 < nkt) {
            int ns = stage + 2; if (ns >= NSTAGE) ns -= NSTAGE;
            issue(ns, kt + 2);
            CP_COMMIT();
        }

#pragma unroll
        for (int mi = 0; mi < 4; mi++)
#pragma unroll
            for (int nj = 0; nj < 4; nj++)
                mma_f16(acc[mi][nj], av[mi], bv[nj][0], bv[nj][1]);

#pragma unroll
        for (int s = 1; s < 4; s++) {
#pragma unroll
            for (int mi = 0; mi < 4; mi++)
                ldsm4(av[mi][0], av[mi][1], av[mi][2], av[mi][3],
                      aBase + mi * (16 * GSTR * 4) + s * 32);
            ldsm4(bv[0][0], bv[0][1], bv[1][0], bv[1][1], bBase + s * 32);
            ldsm4(bv[2][0], bv[2][1], bv[3][0], bv[3][1],
                  bBase + 16 * GSTR * 4 + s * 32);
#pragma unroll
            for (int mi = 0; mi < 4; mi++)
#pragma unroll
                for (int nj = 0; nj < 4; nj++)
                    mma_f16(acc[mi][nj], av[mi], bv[nj][0], bv[nj][1]);
        }
        stage++; if (stage >= NSTAGE) stage -= NSTAGE;
    }

    // epilogue
#pragma unroll
    for (int mi = 0; mi < 4; mi++) {
        const int r = m0 + wm * 64 + 16 * mi + gid;
#pragma unroll
        for (int nj = 0; nj < 4; nj++) {
            const int c = n0 + wn * 32 + 8 * nj + 2 * tig;
            if (MODE == 0) {
                float* C = (float*)C0;
                *(float2*)(C + (size_t)r * N + c) =
                    make_float2(acc[mi][nj][0], acc[mi][nj][1]);
                *(float2*)(C + (size_t)(r + 8) * N + c) =
                    make_float2(acc[mi][nj][2], acc[mi][nj][3]);
            } else {
                if (n0 < 2 * D_MODEL) {   // Q|K -> fp16, stride 2048
                    __half2* C = (__half2*)C0;
                    C[((size_t)r * 2048 + c) >> 1] =
                        __floats2half2_rn(acc[mi][nj][0], acc[mi][nj][1]);
                    C[((size_t)(r + 8) * 2048 + c) >> 1] =
                        __floats2half2_rn(acc[mi][nj][2], acc[mi][nj][3]);
                } else {                  // V -> transposed fp16: vt[(b*1024+d)][s]
                    __half* VT = (__half*)C1;
                    const int dg = c - 2 * D_MODEL;
                    const size_t base =
                        ((size_t)(r >> 11) * D_MODEL + dg) * SEQ + (r & 2047);
                    VT[base]            = __float2half_rn(acc[mi][nj][0]);
                    VT[base + SEQ]      = __float2half_rn(acc[mi][nj][1]);
                    VT[base + 8]        = __float2half_rn(acc[mi][nj][2]);
                    VT[base + SEQ + 8]  = __float2half_rn(acc[mi][nj][3]);
                }
            }
        }
    }
}

// ---------------------------------------------------------------------------
// Causal flash attention, all-fp16 mma, register-resident P, ldmatrix frags.
// 128-query tiles, 256 threads (8 warps x 16 rows), paired key tiles
// (4 buffers, one wait+sync per 2 tiles), per-warp causal skip, base-2 softmax.
// LOAD BALANCE: each block runs q-tiles (NQT-1-bx) then bx -> uniform wave.
// __launch_bounds__(256,2) forces regs<=128 so 2 CTAs/SM (one full wave).
// ---------------------------------------------------------------------------
#define AKS 36
#define AKS_ELEMS (64 * AKS)
#define AVS 36
#define AVS_ELEMS (64 * AVS)
#define AQS 36
#define QROWS 128
#define NQT (SEQ / QROWS)     // 16
#define SMEM_ATTN ((4 * AKS_ELEMS + 4 * AVS_ELEMS + QROWS * AQS) * 4)   // 92160 B

__global__ __launch_bounds__(256, 2)
void attn_h(const __half* __restrict__ qk, const __half* __restrict__ vt,
            __half* __restrict__ out) {
    extern __shared__ unsigned sma[];
    unsigned* KsB = sma;                                 // [4][64][AKS]
    unsigned* VsB = sma + 4 * AKS_ELEMS;                 // [4][64 d][AVS]
    unsigned* Qs  = sma + 4 * AKS_ELEMS + 4 * AVS_ELEMS; // [128][AQS]
    const unsigned smb = (unsigned)__cvta_generic_to_shared(sma);

    const int h    = blockIdx.y;
    const int b    = blockIdx.z;
    const int t    = threadIdx.x;
    const int lane = t & 31;
    const int w    = t >> 5;        // 0..7
    const int gid  = lane >> 2;
    const int tig  = lane & 3;

    const int li  = lane & 7;
    const int q8  = (lane >> 3) & 1;
    const int q16 = lane >> 4;
    const unsigned kLane = ((unsigned)((q16 * 8 + li) * AKS + q8 * 4)) * 4;
    const unsigned vLane = ((unsigned)((q16 * 8 + li) * AVS + q8 * 4)) * 4;

    const __half* kbase  = qk + (size_t)(b * SEQ) * 2048 + D_MODEL + h * HD;
    const __half* vtbase = vt + ((size_t)b * D_MODEL + h * HD) * SEQ;

    auto load_kv = [&](int nb, int jt) {
        const __half* kp = kbase + (size_t)jt * 64 * 2048;
        const __half* vp = vtbase + jt * 64;
#pragma unroll
        for (int i = 0; i < 2; i++) {       // K: 64 rows x 8 chunks = 512
            const int c = t + i * 256;
            const int row = c >> 3, cc = c & 7;
            cp_async16(&KsB[nb * AKS_ELEMS + row * AKS + cc * 4],
                       kp + (size_t)row * 2048 + cc * 8);
        }
#pragma unroll
        for (int i = 0; i < 2; i++) {       // V^T: 64 d-rows x 8 chunks = 512
            const int c = t + i * 256;
            const int row = c >> 3, cc = c & 7;
            cp_async16(&VsB[nb * AVS_ELEMS + row * AVS + cc * 4],
                       vp + (size_t)row * SEQ + cc * 8);
        }
    };

    for (int leg = 0; leg < 2; leg++) {
        const int qt = leg ? (int)blockIdx.x : (NQT - 1 - (int)blockIdx.x);
        const int q0 = qt * QROWS;

        __syncthreads();   // previous leg's buffer reads fully done

        // prologue: Q tile (128 rows) + key-tile pair 0 (tiles 0,1 -> bufs 0,1)
        {
            const __half* qp = qk + (size_t)(b * SEQ + q0) * 2048 + h * HD;
#pragma unroll
            for (int i = 0; i < 4; i++) {       // Q: 128 rows x 8 chunks = 1024
                const int c = t + i * 256;
                const int row = c >> 3, cc = c & 7;
                cp_async16(&Qs[row * AQS + cc * 4], qp + (size_t)row * 2048 + cc * 8);
            }
            load_kv(0, 0);
            load_kv(1, 1);
        }
        CP_COMMIT();
        CP_WAIT0();
        __syncthreads();

        // Q fragments -> registers, scaled by 0.125*log2(e) (base-2 softmax)
        unsigned qf[4][4];
        {
            const __half2 sc = __float2half2_rn(0.125f * 1.44269504f);
            const int r0 = (16 * w + gid) * AQS;
            const int r1 = (16 * w + gid + 8) * AQS;
#pragma unroll
            for (int s = 0; s < 4; s++) {
                unsigned u0 = Qs[r0 + 8 * s + tig];
                unsigned u1 = Qs[r1 + 8 * s + tig];
                unsigned u2 = Qs[r0 + 8 * s + tig + 4];
                unsigned u3 = Qs[r1 + 8 * s + tig + 4];
                __half2 h0 = __hmul2(*(__half2*)&u0, sc);
                __half2 h1 = __hmul2(*(__half2*)&u1, sc);
                __half2 h2 = __hmul2(*(__half2*)&u2, sc);
                __half2 h3 = __hmul2(*(__half2*)&u3, sc);
                qf[s][0] = *(unsigned*)&h0;
                qf[s][1] = *(unsigned*)&h1;
                qf[s][2] = *(unsigned*)&h2;
                qf[s][3] = *(unsigned*)&h3;
            }
        }

        float o[8][4];
#pragma unroll
        for (int j = 0; j < 8; j++)
#pragma unroll
            for (int e = 0; e < 4; e++) o[j][e] = 0.f;
        float m0 = -1e30f, m1 = -1e30f, l0 = 0.f, l1 = 0.f;

        const int row0    = q0 + 16 * w + gid;
        const int rowWmin = q0 + 16 * w;
        const int rowWmax = rowWmin + 15;
        const int npair   = qt + 1;

        for (int p = 0; p < npair; p++) {
            CP_WAIT0();
            __syncthreads();

            if (p + 1 < npair) {
                const int nb = 2 * ((p + 1) & 1);
                load_kv(nb,     2 * p + 2);
                load_kv(nb + 1, 2 * p + 3);
                CP_COMMIT();
            }

#pragma unroll
            for (int half = 0; half < 2; half++) {
                const int jt = 2 * p + half;
                const int k0 = jt * 64;
                if (k0 > rowWmax) continue;   // fully above diagonal: exact no-op

                const int buf = 2 * (p & 1) + half;
                const unsigned kBase = smb + (unsigned)(buf * AKS_ELEMS) * 4 + kLane;
                const unsigned vBase = smb + (unsigned)(4 * AKS_ELEMS + buf * AVS_ELEMS) * 4 + vLane;

                // S = Q K^T
                float sacc[8][4];
#pragma unroll
                for (int j = 0; j < 8; j++)
#pragma unroll
                    for (int e = 0; e < 4; e++) sacc[j][e] = 0.f;

#pragma unroll
                for (int s = 0; s < 4; s++) {
#pragma unroll
                    for (int pp = 0; pp < 4; pp++) {
                        unsigned k0r, k1r, k2r, k3r;
                        ldsm4(k0r, k1r, k2r, k3r, kBase + pp * (16 * AKS * 4) + s * 32);
                        mma_f16(sacc[2 * pp],     qf[s], k0r, k1r);
                        mma_f16(sacc[2 * pp + 1], qf[s], k2r, k3r);
                    }
                }

                // mask + row max
                const bool need_mask = (k0 + 63 > rowWmin);
                float mt0 = -1e30f, mt1 = -1e30f;
#pragma unroll
                for (int j = 0; j < 8; j++) {
                    const int cb = k0 + 8 * j + 2 * tig;
                    if (need_mask) {
                        if (cb     > row0)     sacc[j][0] = -1e30f;
                        if (cb + 1 > row0)     sacc[j][1] = -1e30f;
                        if (cb     > row0 + 8) sacc[j][2] = -1e30f;
                        if (cb + 1 > row0 + 8) sacc[j][3] = -1e30f;
                    }
                    mt0 = fmaxf(mt0, fmaxf(sacc[j][0], sacc[j][1]));
                    mt1 = fmaxf(mt1, fmaxf(sacc[j][2], sacc[j][3]));
                }
                mt0 = fmaxf(mt0, __shfl_xor_sync(0xffffffffu, mt0, 1));
                mt0 = fmaxf(mt0, __shfl_xor_sync(0xffffffffu, mt0, 2));
                mt1 = fmaxf(mt1, __shfl_xor_sync(0xffffffffu, mt1, 1));
                mt1 = fmaxf(mt1, __shfl_xor_sync(0xffffffffu, mt1, 2));

                const float mn0 = fmaxf(m0, mt0);
                const float mn1 = fmaxf(m1, mt1);
                const float al0 = fexp2(m0 - mn0);
                const float al1 = fexp2(m1 - mn1);
                m0 = mn0; m1 = mn1;

                // P = 2^(S - m): fp16 A-fragments in registers
                unsigned pf[4][4];
                float ls0 = 0.f, ls1 = 0.f;
#pragma unroll
                for (int j = 0; j < 8; j++) {
                    float p00 = fexp2(sacc[j][0] - mn0);
                    float p01 = fexp2(sacc[j][1] - mn0);
                    float p10 = fexp2(sacc[j][2] - mn1);
                    float p11 = fexp2(sacc[j][3] - mn1);
                    ls0 += p00 + p01;
                    ls1 += p10 + p11;
                    __half2 lo = __floats2half2_rn(p00, p01);
                    __half2 hi = __floats2half2_rn(p10, p11);
                    const int mm = j >> 1;
                    const int off = (j & 1) << 1;
                    pf[mm][off]     = *(unsigned*)&lo;
                    pf[mm][off + 1] = *(unsigned*)&hi;
                }
                ls0 += __shfl_xor_sync(0xffffffffu, ls0, 1);
                ls0 += __shfl_xor_sync(0xffffffffu, ls0, 2);
                ls1 += __shfl_xor_sync(0xffffffffu, ls1, 1);
                ls1 += __shfl_xor_sync(0xffffffffu, ls1, 2);
                l0 = l0 * al0 + ls0;
                l1 = l1 * al1 + ls1;

#pragma unroll
                for (int j = 0; j < 8; j++) {
                    o[j][0] *= al0; o[j][1] *= al0;
                    o[j][2] *= al1; o[j][3] *= al1;
                }

                // O += P V
#pragma unroll
                for (int mm = 0; mm < 4; mm++) {
#pragma unroll
                    for (int pp = 0; pp < 4; pp++) {
                        unsigned v0, v1, v2, v3;
                        ldsm4(v0, v1, v2, v3, vBase + pp * (16 * AVS * 4) + mm * 32);
                        mma_f16(o[2 * pp],     pf[mm], v0, v1);
                        mma_f16(o[2 * pp + 1], pf[mm], v2, v3);
                    }
                }
            }
        }

        // epilogue -> fp16 for the output projection
        const float i0 = 1.f / l0;
        const float i1 = 1.f / l1;
        __half2* op0 = (__half2*)(out + (size_t)(b * SEQ + row0) * D_MODEL + h * HD);
        __half2* op1 = (__half2*)(out + (size_t)(b * SEQ + row0 + 8) * D_MODEL + h * HD);
#pragma unroll
        for (int j = 0; j < 8; j++) {
            const int c = (8 * j + 2 * tig) >> 1;
            op0[c] = __floats2half2_rn(o[j][0] * i0, o[j][1] * i0);
            op1[c] = __floats2half2_rn(o[j][2] * i1, o[j][3] * i1);
        }
    }
}

extern "C" void kernel_launch(void* const* d_in, const int* in_sizes, int n_in,
                              void* d_out, int out_size) {
    const float* x     = (const float*)d_in[0];
    const float* w_qkv = (const float*)d_in[1];
    const float* w_o   = (const float*)d_in[2];
    float* out         = (float*)d_out;

    __half *qkh, *vt, *ao, *xh, *wqh, *woh;
    cudaGetSymbolAddress((void**)&qkh, g_qkh);
    cudaGetSymbolAddress((void**)&vt,  g_vt);
    cudaGetSymbolAddress((void**)&ao,  g_ao);
    cudaGetSymbolAddress((void**)&xh,  g_xh);
    cudaGetSymbolAddress((void**)&wqh, g_wqh);
    cudaGetSymbolAddress((void**)&woh, g_woh);

    static bool attr_set = false;
    if (!attr_set) {
        cudaFuncSetAttribute(gemm_h<0>, cudaFuncAttributeMaxDynamicSharedMemorySize, SMEM_GEMM);
        cudaFuncSetAttribute(gemm_h<1>, cudaFuncAttributeMaxDynamicSharedMemorySize, SMEM_GEMM);
        cudaFuncSetAttribute(attn_h, cudaFuncAttributeMaxDynamicSharedMemorySize, SMEM_ATTN);
        attr_set = true;
    }

    // 0) fp32 -> fp16 pre-pass
    conv_h<<<CONV_BLOCKS, 256>>>((const float4*)x, (const float4*)w_qkv, (const float4*)w_o,
                                 (uint2*)xh, (uint2*)wqh, (uint2*)woh);

    // 1) QKV projection (fp16 mma): Q|K -> fp16, V -> transposed fp16
    gemm_h<1><<<dim3(QKV_W / 128, M_TOT / 128), 256, SMEM_GEMM>>>(
        xh, wqh, qkh, vt, M_TOT, QKV_W, D_MODEL);

    // 2) causal attention -> fp16 (paired q-tiles: uniform work per block)
    attn_h<<<dim3(NQT / 2, NHEAD, BATCH), 256, SMEM_ATTN>>>(qkh, vt, ao);

    // 3) output projection (fp16 mma) -> fp32
    gemm_h<0><<<dim3(D_MODEL / 128, M_TOT / 128), 256, SMEM_GEMM>>>(
        ao, woh, out, nullptr, M_TOT, D_MODEL, D_MODEL);
}